// round 16
// baseline (speedup 1.0000x reference)
#include <cuda_runtime.h>
#include <cuda_fp16.h>
#include <stdint.h>

#define NEXP 8
#define DIN 1024
#define DHID 4096
#define DOUT 1024
#define NTOK 16384
#define NPAIR 32768
#define MAXT 264

// ---------------- scratch (static device globals; no allocation) ----------
__device__ __half g_hh[134217728];             // 32768 x 4096 fp16 hidden (256MB)
__device__ __half g_xh[NTOK * DIN];            // fp16 x (32MB)
__device__ __half g_w1h[NEXP * DIN * DHID];    // w1^T [e][N=4096][K=1024] (64MB)
__device__ __half g_w2h[NEXP * DHID * DOUT];   // w2^T [e][N=1024][K=4096] (64MB)
__device__ int   g_pair_tok[NPAIR];
__device__ float g_pair_w[NPAIR];
__device__ int   g_tile_e[MAXT];
__device__ int   g_tile_start[MAXT];
__device__ int   g_tile_rows[MAXT];
__device__ int   g_ntiles;
__device__ int   g_top_idx[NTOK * 2];
__device__ float g_top_w[NTOK * 2];

// ---------------- gate: top-2 + softmax weights per token ----------------
__global__ void gate_kernel(const float* __restrict__ x,
                            const float* __restrict__ gw,
                            const float* __restrict__ gb) {
  int warp = threadIdx.x >> 5, lane = threadIdx.x & 31;
  int tok = blockIdx.x * 4 + warp;
  const float* xr = x + (size_t)tok * DIN;
  float acc[NEXP];
#pragma unroll
  for (int e = 0; e < NEXP; e++) acc[e] = 0.f;
  for (int k = lane; k < DIN; k += 32) {
    float xv = xr[k];
    const float* w = gw + k * NEXP;
#pragma unroll
    for (int e = 0; e < NEXP; e++) acc[e] += xv * w[e];
  }
#pragma unroll
  for (int e = 0; e < NEXP; e++) {
#pragma unroll
    for (int off = 16; off > 0; off >>= 1)
      acc[e] += __shfl_down_sync(0xffffffffu, acc[e], off);
  }
  if (lane == 0) {
    float v[NEXP];
#pragma unroll
    for (int e = 0; e < NEXP; e++) v[e] = acc[e] + gb[e];
    int i0 = 0;
#pragma unroll
    for (int e = 1; e < NEXP; e++) if (v[e] > v[i0]) i0 = e;
    int i1 = (i0 == 0) ? 1 : 0;
#pragma unroll
    for (int e = 0; e < NEXP; e++)
      if (e != i0 && v[e] > v[i1]) i1 = e;
    float ee = expf(v[i1] - v[i0]);
    float w0 = 1.f / (1.f + ee);
    float w1 = ee * w0;
    g_top_idx[tok * 2]     = i0;
    g_top_idx[tok * 2 + 1] = i1;
    g_top_w[tok * 2]       = w0;
    g_top_w[tok * 2 + 1]   = w1;
  }
}

// ---------------- route: warp-aggregated count + scan + scatter ----------
__global__ void route_kernel() {
  __shared__ int cnt[NEXP];
  __shared__ int cur[NEXP];
  int tid = threadIdx.x, lane = tid & 31;
  if (tid < NEXP) cnt[tid] = 0;
  __syncthreads();
  for (int i = tid; i < NPAIR; i += 256) {
    int e = g_top_idx[i];
    unsigned m = __match_any_sync(0xffffffffu, e);
    if ((int)(__ffs(m) - 1) == lane) atomicAdd(&cnt[e], __popc(m));
  }
  __syncthreads();
  if (tid == 0) {
    int off = 0, nt = 0;
    for (int e = 0; e < NEXP; e++) {
      int mcount = cnt[e];
      cur[e] = off;
      for (int r = 0; r < mcount; r += 128) {
        g_tile_e[nt]     = e;
        g_tile_start[nt] = off + r;
        g_tile_rows[nt]  = (mcount - r < 128) ? (mcount - r) : 128;
        nt++;
      }
      off += mcount;
    }
    g_ntiles = nt;
  }
  __syncthreads();
  for (int i = tid; i < NPAIR; i += 256) {
    int e = g_top_idx[i];
    unsigned m = __match_any_sync(0xffffffffu, e);
    int leader = __ffs(m) - 1;
    int rank = __popc(m & ((1u << lane) - 1u));
    int base = 0;
    if (lane == leader) base = atomicAdd(&cur[e], __popc(m));
    base = __shfl_sync(0xffffffffu, base, leader);
    int pos = base + rank;
    g_pair_tok[pos] = i >> 1;
    g_pair_w[pos]   = g_top_w[i];
  }
}

// ---------------- fused prep: zero out + x->fp16 + w transposes ----------
#define NB_OUT 16384
#define NB_X   8192
#define NB_W1  32768
#define NB_W2  32768

__device__ __forceinline__ void trt32(const float* S, __half* D, int R, int C,
                                      int r0, int c0, int tid) {
  __shared__ __half t[32][33];   // t[col][row] = S[r0+row][c0+col]
  int tx = tid & 31, ty = tid >> 5;
#pragma unroll
  for (int i = 0; i < 4; i++)
    t[tx][ty + 8 * i] = __float2half_rn(S[(size_t)(r0 + ty + 8 * i) * C + c0 + tx]);
  __syncthreads();
  // write phase: half2-vectorized along R; 512 half2 total, 2 per thread
  // D[c0+cl][r0+2c2 .. 2c2+1] = S[r0+2c2..][c0+cl] = t[cl][2c2], t[cl][2c2+1]
#pragma unroll
  for (int j = 0; j < 2; j++) {
    int idx = tid + j * 256;
    int cl = idx >> 4;           // local output row (C dim), 0..31
    int c2 = idx & 15;           // half2 index along R, 0..15
    __half2 v = __halves2half2(t[cl][2 * c2], t[cl][2 * c2 + 1]);
    *(__half2*)(D + (size_t)(c0 + cl) * R + r0 + 2 * c2) = v;
  }
}

__global__ void prep_kernel(float* __restrict__ out, const float* __restrict__ x,
                            const float* __restrict__ w1, const float* __restrict__ w2) {
  int b = blockIdx.x, tid = threadIdx.x;
  if (b < NB_OUT) {
    ((float4*)out)[(size_t)b * 256 + tid] = make_float4(0.f, 0.f, 0.f, 0.f);
  } else if (b < NB_OUT + NB_X) {
    size_t i = (size_t)(b - NB_OUT) * 256 + tid;
    float4 v0 = ((const float4*)x)[2 * i];
    float4 v1 = ((const float4*)x)[2 * i + 1];
    __half2 h[4];
    h[0] = __floats2half2_rn(v0.x, v0.y);
    h[1] = __floats2half2_rn(v0.z, v0.w);
    h[2] = __floats2half2_rn(v1.x, v1.y);
    h[3] = __floats2half2_rn(v1.z, v1.w);
    ((uint4*)g_xh)[i] = *(uint4*)h;
  } else if (b < NB_OUT + NB_X + NB_W1) {
    int r = b - NB_OUT - NB_X;
    int e = r >> 12, rem = r & 4095;
    int cx = rem & 127, cy = rem >> 7;
    trt32(w1 + (size_t)e * DIN * DHID, g_w1h + (size_t)e * DIN * DHID,
          DIN, DHID, cy * 32, cx * 32, tid);
  } else {
    int r = b - NB_OUT - NB_X - NB_W1;
    int e = r >> 12, rem = r & 4095;
    int cx = rem & 31, cy = rem >> 5;
    trt32(w2 + (size_t)e * DHID * DOUT, g_w2h + (size_t)e * DHID * DOUT,
          DHID, DOUT, cy * 32, cx * 32, tid);
  }
}

// ---------------- fp16 mma.sync GEMM (BK=32, 5-stage, ldmatrix frags) ----
#define MMA_F16(d, a, b)                                                     \
  asm volatile(                                                              \
      "mma.sync.aligned.m16n8k16.row.col.f32.f16.f16.f32 "                   \
      "{%0,%1,%2,%3},{%4,%5,%6,%7},{%8,%9},{%0,%1,%2,%3};"                   \
      : "+f"(d[0]), "+f"(d[1]), "+f"(d[2]), "+f"(d[3])                       \
      : "r"(a[0]), "r"(a[1]), "r"(a[2]), "r"(a[3]), "r"(b[0]), "r"(b[1]))

__device__ __forceinline__ void ldsm4(uint32_t* r, uint32_t addr) {
  asm volatile("ldmatrix.sync.aligned.m8n8.x4.shared.b16 {%0,%1,%2,%3}, [%4];"
               : "=r"(r[0]), "=r"(r[1]), "=r"(r[2]), "=r"(r[3]) : "r"(addr));
}

// MODE 0: A = gathered g_xh rows, h = relu(A@w1^T+b1) -> g_hh (fp16)
// MODE 1: A = g_hh rows,          out += gatew * (A@w2^T+b2)  (atomic)
template <int MODE>
__global__ __launch_bounds__(256, 2) void moe_mma(const float* __restrict__ Bias,
                                                  float* __restrict__ Out) {
  constexpr int KDIM = (MODE == 0) ? DIN : DHID;
  constexpr int NDIM = (MODE == 0) ? DHID : DOUT;
  constexpr int BK = 32, S = 5;
  constexpr int KT = KDIM / BK;
  constexpr int AST = 40;             // halfs per smem row (20 banks -> cf)
  constexpr int STAGE_H = 2 * 128 * AST;  // A tile + B tile, in halfs
  extern __shared__ __half smh[];

  int tile = blockIdx.y;
  if (tile >= g_ntiles) return;
  int e = g_tile_e[tile], pstart = g_tile_start[tile], rows = g_tile_rows[tile];
  int n0 = blockIdx.x * 128;
  int tid = threadIdx.x;
  int lane = tid & 31, warp = tid >> 5;
  int g = lane >> 2, t = lane & 3;
  int wm = warp >> 2, wn = warp & 3;  // 2 x 4 warps, warp tile 64x32

  const __half* Bsrc = ((MODE == 0) ? g_w1h : g_w2h) + (size_t)e * KDIM * NDIM;

  // loads: each thread owns row (tid>>1) of A and of B, half (tid&1)
  int lrow = tid >> 1;
  int off16 = (tid & 1) * 16;
  bool av = lrow < rows;
  const __half* aptr;
  if (MODE == 0) {
    int tok = av ? g_pair_tok[pstart + lrow] : 0;
    aptr = g_xh + (size_t)tok * DIN + off16;
  } else {
    aptr = g_hh + (size_t)(pstart + (av ? lrow : 0)) * DHID + off16;
  }
  int abytes = av ? 16 : 0;
  const __half* bptr = Bsrc + (size_t)(n0 + lrow) * KDIM + off16;

  uint32_t sb;
  asm("{ .reg .u64 t; cvta.to.shared.u64 t, %1; cvt.u32.u64 %0, t; }"
      : "=r"(sb) : "l"(smh));
  uint32_t adst = sb + (uint32_t)(lrow * AST + off16) * 2;
  uint32_t bdst = adst + 128 * AST * 2;

  auto issue = [&](int c, int s) {
    uint32_t o = (uint32_t)s * (STAGE_H * 2);
    asm volatile("cp.async.cg.shared.global [%0], [%1], 16, %2;"
                 ::"r"(adst + o), "l"(aptr + c * 32), "r"(abytes));
    asm volatile("cp.async.cg.shared.global [%0], [%1], 16, %2;"
                 ::"r"(adst + o + 16), "l"(aptr + c * 32 + 8), "r"(abytes));
    asm volatile("cp.async.cg.shared.global [%0], [%1], 16;"
                 ::"r"(bdst + o), "l"(bptr + c * 32));
    asm volatile("cp.async.cg.shared.global [%0], [%1], 16;"
                 ::"r"(bdst + o + 16), "l"(bptr + c * 32 + 8));
  };

  // per-lane ldmatrix base offsets (bytes within a stage)
  int ra = (lane & 7) + ((lane >> 3) & 1) * 8;   // A row-in-16 component
  int ka = ((lane >> 4) & 1) * 8;                // A k component (halfs)
  int rb = (lane & 7) + ((lane >> 4) & 1) * 8;   // B n-row component
  int kb = ((lane >> 3) & 1) * 8;                // B k component (halfs)
  uint32_t a_off[4], b_off[2];
#pragma unroll
  for (int mi = 0; mi < 4; mi++)
    a_off[mi] = (uint32_t)(((wm * 64 + mi * 16 + ra) * AST + ka) * 2);
#pragma unroll
  for (int p = 0; p < 2; p++)
    b_off[p] = (uint32_t)(128 * AST * 2) +
               (uint32_t)(((wn * 32 + p * 16 + rb) * AST + kb) * 2);

  float acc[4][4][4];
#pragma unroll
  for (int i = 0; i < 4; i++)
#pragma unroll
    for (int j = 0; j < 4; j++)
#pragma unroll
      for (int q = 0; q < 4; q++) acc[i][j][q] = 0.f;

#pragma unroll
  for (int c = 0; c < S - 1; c++) {
    issue(c, c);
    asm volatile("cp.async.commit_group;");
  }

#pragma unroll 1
  for (int k = 0; k < KT; k++) {
    asm volatile("cp.async.wait_group %0;" ::"n"(S - 2));
    __syncthreads();
    // prefetch next chunk early: stage (k-1)%S was fully consumed at the sync
    int lc = k + S - 1;
    if (lc < KT) issue(lc, lc % S);
    asm volatile("cp.async.commit_group;");
    uint32_t stage = sb + (uint32_t)(k % S) * (STAGE_H * 2);
#pragma unroll
    for (int ks = 0; ks < 2; ks++) {
      uint32_t kso = (uint32_t)(ks * 32);  // 16 halfs per ks
      uint32_t af[4][4], bf[4][2];
#pragma unroll
      for (int mi = 0; mi < 4; mi++) ldsm4(af[mi], stage + a_off[mi] + kso);
#pragma unroll
      for (int p = 0; p < 2; p++) {
        uint32_t r[4];
        ldsm4(r, stage + b_off[p] + kso);
        bf[2 * p][0] = r[0]; bf[2 * p][1] = r[1];
        bf[2 * p + 1][0] = r[2]; bf[2 * p + 1][1] = r[3];
      }
#pragma unroll
      for (int mi = 0; mi < 4; mi++)
#pragma unroll
        for (int ni = 0; ni < 4; ni++) MMA_F16(acc[mi][ni], af[mi], bf[ni]);
    }
  }

  // ---------------- epilogue ----------------
#pragma unroll
  for (int mi = 0; mi < 4; mi++) {
#pragma unroll
    for (int j2 = 0; j2 < 2; j2++) {
      int r = wm * 64 + mi * 16 + g + j2 * 8;
      if (r >= rows) continue;
      int p = pstart + r;
      int tok = 0;
      float wgt = 0.f;
      if (MODE == 1) { tok = g_pair_tok[p]; wgt = g_pair_w[p]; }
#pragma unroll
      for (int ni = 0; ni < 4; ni++) {
        int c = wn * 32 + ni * 8 + t * 2;
        const float* bp = Bias + (size_t)e * NDIM + n0 + c;
        float v0 = acc[mi][ni][j2 * 2]     + bp[0];
        float v1 = acc[mi][ni][j2 * 2 + 1] + bp[1];
        if (MODE == 0) {
          __half2 hv = __floats2half2_rn(fmaxf(v0, 0.f), fmaxf(v1, 0.f));
          *(__half2*)(g_hh + (size_t)p * DHID + n0 + c) = hv;
        } else {
          float* op = Out + (size_t)tok * DOUT + n0 + c;
          atomicAdd(op, wgt * v0);
          atomicAdd(op + 1, wgt * v1);
        }
      }
    }
  }
}

// ---------------- launch ----------------
extern "C" void kernel_launch(void* const* d_in, const int* in_sizes, int n_in,
                              void* d_out, int out_size) {
  const float* x  = (const float*)d_in[0];
  const float* gw = (const float*)d_in[1];
  const float* gb = (const float*)d_in[2];
  const float* w1 = (const float*)d_in[3];
  const float* b1 = (const float*)d_in[4];
  const float* w2 = (const float*)d_in[5];
  const float* b2 = (const float*)d_in[6];
  float* out = (float*)d_out;

  gate_kernel<<<NTOK / 4, 128>>>(x, gw, gb);                            // 0
  route_kernel<<<1, 256>>>();                                           // 1
  prep_kernel<<<NB_OUT + NB_X + NB_W1 + NB_W2, 256>>>(out, x, w1, w2);  // 2

  const int smem = 5 * 2 * 128 * 40 * 2;  // 102400 B
  cudaFuncSetAttribute(moe_mma<0>, cudaFuncAttributeMaxDynamicSharedMemorySize, smem);
  cudaFuncSetAttribute(moe_mma<1>, cudaFuncAttributeMaxDynamicSharedMemorySize, smem);
  moe_mma<0><<<dim3(DHID / 128, MAXT), 256, smem>>>(b1, nullptr);       // 3 (ncu slot)
  moe_mma<1><<<dim3(DOUT / 128, MAXT), 256, smem>>>(b2, out);           // 4
}

// round 17
// speedup vs baseline: 1.0690x; 1.0690x over previous
#include <cuda_runtime.h>
#include <cuda_fp16.h>
#include <stdint.h>

#define NEXP 8
#define DIN 1024
#define DHID 4096
#define DOUT 1024
#define NTOK 16384
#define NPAIR 32768
#define MAXT 264

// ---------------- scratch (static device globals; no allocation) ----------
__device__ __half g_hh[134217728];             // 32768 x 4096 fp16 hidden (256MB)
__device__ __half g_xh[NTOK * DIN];            // fp16 x (32MB)
__device__ __half g_w1h[NEXP * DIN * DHID];    // w1^T [e][N=4096][K=1024] (64MB)
__device__ __half g_w2h[NEXP * DHID * DOUT];   // w2^T [e][N=1024][K=4096] (64MB)
__device__ int   g_pair_tok[NPAIR];
__device__ float g_pair_w[NPAIR];
__device__ int   g_tile_e[MAXT];
__device__ int   g_tile_start[MAXT];
__device__ int   g_tile_rows[MAXT];
__device__ int   g_ntiles;
__device__ int   g_top_idx[NTOK * 2];
__device__ float g_top_w[NTOK * 2];

// ---------------- gate: top-2 + softmax weights per token ----------------
__global__ void gate_kernel(const float* __restrict__ x,
                            const float* __restrict__ gw,
                            const float* __restrict__ gb) {
  int warp = threadIdx.x >> 5, lane = threadIdx.x & 31;
  int tok = blockIdx.x * 4 + warp;
  const float* xr = x + (size_t)tok * DIN;
  float acc[NEXP];
#pragma unroll
  for (int e = 0; e < NEXP; e++) acc[e] = 0.f;
  for (int k = lane; k < DIN; k += 32) {
    float xv = xr[k];
    const float* w = gw + k * NEXP;
#pragma unroll
    for (int e = 0; e < NEXP; e++) acc[e] += xv * w[e];
  }
#pragma unroll
  for (int e = 0; e < NEXP; e++) {
#pragma unroll
    for (int off = 16; off > 0; off >>= 1)
      acc[e] += __shfl_down_sync(0xffffffffu, acc[e], off);
  }
  if (lane == 0) {
    float v[NEXP];
#pragma unroll
    for (int e = 0; e < NEXP; e++) v[e] = acc[e] + gb[e];
    int i0 = 0;
#pragma unroll
    for (int e = 1; e < NEXP; e++) if (v[e] > v[i0]) i0 = e;
    int i1 = (i0 == 0) ? 1 : 0;
#pragma unroll
    for (int e = 0; e < NEXP; e++)
      if (e != i0 && v[e] > v[i1]) i1 = e;
    float ee = expf(v[i1] - v[i0]);
    float w0 = 1.f / (1.f + ee);
    float w1 = ee * w0;
    g_top_idx[tok * 2]     = i0;
    g_top_idx[tok * 2 + 1] = i1;
    g_top_w[tok * 2]       = w0;
    g_top_w[tok * 2 + 1]   = w1;
  }
}

// ---------------- route: warp-aggregated count + scan + scatter ----------
__global__ void route_kernel() {
  __shared__ int cnt[NEXP];
  __shared__ int cur[NEXP];
  int tid = threadIdx.x, lane = tid & 31;
  if (tid < NEXP) cnt[tid] = 0;
  __syncthreads();
  for (int i = tid; i < NPAIR; i += 256) {
    int e = g_top_idx[i];
    unsigned m = __match_any_sync(0xffffffffu, e);
    if ((int)(__ffs(m) - 1) == lane) atomicAdd(&cnt[e], __popc(m));
  }
  __syncthreads();
  if (tid == 0) {
    int off = 0, nt = 0;
    for (int e = 0; e < NEXP; e++) {
      int mcount = cnt[e];
      cur[e] = off;
      for (int r = 0; r < mcount; r += 128) {
        g_tile_e[nt]     = e;
        g_tile_start[nt] = off + r;
        g_tile_rows[nt]  = (mcount - r < 128) ? (mcount - r) : 128;
        nt++;
      }
      off += mcount;
    }
    g_ntiles = nt;
  }
  __syncthreads();
  for (int i = tid; i < NPAIR; i += 256) {
    int e = g_top_idx[i];
    unsigned m = __match_any_sync(0xffffffffu, e);
    int leader = __ffs(m) - 1;
    int rank = __popc(m & ((1u << lane) - 1u));
    int base = 0;
    if (lane == leader) base = atomicAdd(&cur[e], __popc(m));
    base = __shfl_sync(0xffffffffu, base, leader);
    int pos = base + rank;
    g_pair_tok[pos] = i >> 1;
    g_pair_w[pos]   = g_top_w[i];
  }
}

// ---------------- fused prep: zero out + x->fp16 + w transposes ----------
#define NB_OUT 16384
#define NB_X   8192
#define NB_W1  32768
#define NB_W2  32768

__device__ __forceinline__ void trt32(const float* S, __half* D, int R, int C,
                                      int r0, int c0, int tid) {
  __shared__ __half t[32][33];   // t[col][row] = S[r0+row][c0+col]
  int tx = tid & 31, ty = tid >> 5;
#pragma unroll
  for (int i = 0; i < 4; i++)
    t[tx][ty + 8 * i] = __float2half_rn(S[(size_t)(r0 + ty + 8 * i) * C + c0 + tx]);
  __syncthreads();
  // write phase: half2-vectorized along R; 512 half2 total, 2 per thread
  // D[c0+cl][r0+2c2 .. 2c2+1] = t[cl][2c2], t[cl][2c2+1]
#pragma unroll
  for (int j = 0; j < 2; j++) {
    int idx = tid + j * 256;
    int cl = idx >> 4;           // local output row (C dim), 0..31
    int c2 = idx & 15;           // half2 index along R, 0..15
    __half2 v = __halves2half2(t[cl][2 * c2], t[cl][2 * c2 + 1]);
    *(__half2*)(D + (size_t)(c0 + cl) * R + r0 + 2 * c2) = v;
  }
}

__global__ void prep_kernel(float* __restrict__ out, const float* __restrict__ x,
                            const float* __restrict__ w1, const float* __restrict__ w2) {
  int b = blockIdx.x, tid = threadIdx.x;
  if (b < NB_OUT) {
    ((float4*)out)[(size_t)b * 256 + tid] = make_float4(0.f, 0.f, 0.f, 0.f);
  } else if (b < NB_OUT + NB_X) {
    size_t i = (size_t)(b - NB_OUT) * 256 + tid;
    float4 v0 = ((const float4*)x)[2 * i];
    float4 v1 = ((const float4*)x)[2 * i + 1];
    __half2 h[4];
    h[0] = __floats2half2_rn(v0.x, v0.y);
    h[1] = __floats2half2_rn(v0.z, v0.w);
    h[2] = __floats2half2_rn(v1.x, v1.y);
    h[3] = __floats2half2_rn(v1.z, v1.w);
    ((uint4*)g_xh)[i] = *(uint4*)h;
  } else if (b < NB_OUT + NB_X + NB_W1) {
    int r = b - NB_OUT - NB_X;
    int e = r >> 12, rem = r & 4095;
    int cx = rem & 127, cy = rem >> 7;
    trt32(w1 + (size_t)e * DIN * DHID, g_w1h + (size_t)e * DIN * DHID,
          DIN, DHID, cy * 32, cx * 32, tid);
  } else {
    int r = b - NB_OUT - NB_X - NB_W1;
    int e = r >> 12, rem = r & 4095;
    int cx = rem & 31, cy = rem >> 5;
    trt32(w2 + (size_t)e * DHID * DOUT, g_w2h + (size_t)e * DHID * DOUT,
          DHID, DOUT, cy * 32, cx * 32, tid);
  }
}

// ---------------- fp16 mma.sync GEMM (BK=32, 4-stage, ldmatrix frags) ----
#define MMA_F16(d, a, b)                                                     \
  asm volatile(                                                              \
      "mma.sync.aligned.m16n8k16.row.col.f32.f16.f16.f32 "                   \
      "{%0,%1,%2,%3},{%4,%5,%6,%7},{%8,%9},{%0,%1,%2,%3};"                   \
      : "+f"(d[0]), "+f"(d[1]), "+f"(d[2]), "+f"(d[3])                       \
      : "r"(a[0]), "r"(a[1]), "r"(a[2]), "r"(a[3]), "r"(b[0]), "r"(b[1]))

__device__ __forceinline__ void ldsm4(uint32_t* r, uint32_t addr) {
  asm volatile("ldmatrix.sync.aligned.m8n8.x4.shared.b16 {%0,%1,%2,%3}, [%4];"
               : "=r"(r[0]), "=r"(r[1]), "=r"(r[2]), "=r"(r[3]) : "r"(addr));
}

// MODE 0: A = gathered g_xh rows, h = relu(A@w1^T+b1) -> g_hh (fp16)
// MODE 1: A = g_hh rows,          out += gatew * (A@w2^T+b2)  (atomic)
template <int MODE>
__global__ __launch_bounds__(256, 2) void moe_mma(const float* __restrict__ Bias,
                                                  float* __restrict__ Out) {
  constexpr int KDIM = (MODE == 0) ? DIN : DHID;
  constexpr int NDIM = (MODE == 0) ? DHID : DOUT;
  constexpr int BK = 32, S = 4;
  constexpr int KT = KDIM / BK;
  constexpr int AST = 40;             // halfs per smem row (20 banks -> cf)
  constexpr int STAGE_H = 2 * 128 * AST;  // A tile + B tile, in halfs
  extern __shared__ __half smh[];

  int tile = blockIdx.y;
  if (tile >= g_ntiles) return;
  int e = g_tile_e[tile], pstart = g_tile_start[tile], rows = g_tile_rows[tile];
  int n0 = blockIdx.x * 128;
  int tid = threadIdx.x;
  int lane = tid & 31, warp = tid >> 5;
  int g = lane >> 2, t = lane & 3;
  int wm = warp >> 2, wn = warp & 3;  // 2 x 4 warps, warp tile 64x32

  const __half* Bsrc = ((MODE == 0) ? g_w1h : g_w2h) + (size_t)e * KDIM * NDIM;

  // loads: each thread owns row (tid>>1) of A and of B, half (tid&1)
  int lrow = tid >> 1;
  int off16 = (tid & 1) * 16;
  bool av = lrow < rows;
  const __half* aptr;
  if (MODE == 0) {
    int tok = av ? g_pair_tok[pstart + lrow] : 0;
    aptr = g_xh + (size_t)tok * DIN + off16;
  } else {
    aptr = g_hh + (size_t)(pstart + (av ? lrow : 0)) * DHID + off16;
  }
  int abytes = av ? 16 : 0;
  const __half* bptr = Bsrc + (size_t)(n0 + lrow) * KDIM + off16;

  uint32_t sb;
  asm("{ .reg .u64 t; cvta.to.shared.u64 t, %1; cvt.u32.u64 %0, t; }"
      : "=r"(sb) : "l"(smh));
  uint32_t adst = sb + (uint32_t)(lrow * AST + off16) * 2;
  uint32_t bdst = adst + 128 * AST * 2;

  auto issue = [&](int c, int s) {
    uint32_t o = (uint32_t)s * (STAGE_H * 2);
    asm volatile("cp.async.cg.shared.global [%0], [%1], 16, %2;"
                 ::"r"(adst + o), "l"(aptr + c * 32), "r"(abytes));
    asm volatile("cp.async.cg.shared.global [%0], [%1], 16, %2;"
                 ::"r"(adst + o + 16), "l"(aptr + c * 32 + 8), "r"(abytes));
    asm volatile("cp.async.cg.shared.global [%0], [%1], 16;"
                 ::"r"(bdst + o), "l"(bptr + c * 32));
    asm volatile("cp.async.cg.shared.global [%0], [%1], 16;"
                 ::"r"(bdst + o + 16), "l"(bptr + c * 32 + 8));
  };

  // per-lane ldmatrix base offsets (bytes within a stage)
  int ra = (lane & 7) + ((lane >> 3) & 1) * 8;   // A row-in-16 component
  int ka = ((lane >> 4) & 1) * 8;                // A k component (halfs)
  int rb = (lane & 7) + ((lane >> 4) & 1) * 8;   // B n-row component
  int kb = ((lane >> 3) & 1) * 8;                // B k component (halfs)
  uint32_t a_off[4], b_off[2];
#pragma unroll
  for (int mi = 0; mi < 4; mi++)
    a_off[mi] = (uint32_t)(((wm * 64 + mi * 16 + ra) * AST + ka) * 2);
#pragma unroll
  for (int p = 0; p < 2; p++)
    b_off[p] = (uint32_t)(128 * AST * 2) +
               (uint32_t)(((wn * 32 + p * 16 + rb) * AST + kb) * 2);

  float acc[4][4][4];
#pragma unroll
  for (int i = 0; i < 4; i++)
#pragma unroll
    for (int j = 0; j < 4; j++)
#pragma unroll
      for (int q = 0; q < 4; q++) acc[i][j][q] = 0.f;

#pragma unroll
  for (int c = 0; c < S - 1; c++) {
    issue(c, c);
    asm volatile("cp.async.commit_group;");
  }

#pragma unroll 1
  for (int k = 0; k < KT; k++) {
    asm volatile("cp.async.wait_group %0;" ::"n"(S - 2));
    __syncthreads();
    uint32_t stage = sb + (uint32_t)(k % S) * (STAGE_H * 2);
#pragma unroll
    for (int ks = 0; ks < 2; ks++) {
      uint32_t kso = (uint32_t)(ks * 32);  // 16 halfs per ks
      uint32_t af[4][4], bf[4][2];
#pragma unroll
      for (int mi = 0; mi < 4; mi++) ldsm4(af[mi], stage + a_off[mi] + kso);
#pragma unroll
      for (int p = 0; p < 2; p++) {
        uint32_t r[4];
        ldsm4(r, stage + b_off[p] + kso);
        bf[2 * p][0] = r[0]; bf[2 * p][1] = r[1];
        bf[2 * p + 1][0] = r[2]; bf[2 * p + 1][1] = r[3];
      }
#pragma unroll
      for (int mi = 0; mi < 4; mi++)
#pragma unroll
        for (int ni = 0; ni < 4; ni++) MMA_F16(acc[mi][ni], af[mi], bf[ni]);
    }
    int lc = k + S - 1;
    if (lc < KT) issue(lc, lc % S);
    asm volatile("cp.async.commit_group;");
  }

  // ---------------- epilogue ----------------
#pragma unroll
  for (int mi = 0; mi < 4; mi++) {
#pragma unroll
    for (int j2 = 0; j2 < 2; j2++) {
      int r = wm * 64 + mi * 16 + g + j2 * 8;
      if (r >= rows) continue;
      int p = pstart + r;
      int tok = 0;
      float wgt = 0.f;
      if (MODE == 1) { tok = g_pair_tok[p]; wgt = g_pair_w[p]; }
#pragma unroll
      for (int ni = 0; ni < 4; ni++) {
        int c = wn * 32 + ni * 8 + t * 2;
        const float* bp = Bias + (size_t)e * NDIM + n0 + c;
        float v0 = acc[mi][ni][j2 * 2]     + bp[0];
        float v1 = acc[mi][ni][j2 * 2 + 1] + bp[1];
        if (MODE == 0) {
          __half2 hv = __floats2half2_rn(fmaxf(v0, 0.f), fmaxf(v1, 0.f));
          *(__half2*)(g_hh + (size_t)p * DHID + n0 + c) = hv;
        } else {
          float* op = Out + (size_t)tok * DOUT + n0 + c;
          atomicAdd(op, wgt * v0);
          atomicAdd(op + 1, wgt * v1);
        }
      }
    }
  }
}

// ---------------- launch ----------------
extern "C" void kernel_launch(void* const* d_in, const int* in_sizes, int n_in,
                              void* d_out, int out_size) {
  const float* x  = (const float*)d_in[0];
  const float* gw = (const float*)d_in[1];
  const float* gb = (const float*)d_in[2];
  const float* w1 = (const float*)d_in[3];
  const float* b1 = (const float*)d_in[4];
  const float* w2 = (const float*)d_in[5];
  const float* b2 = (const float*)d_in[6];
  float* out = (float*)d_out;

  gate_kernel<<<NTOK / 4, 128>>>(x, gw, gb);                            // 0
  route_kernel<<<1, 256>>>();                                           // 1
  prep_kernel<<<NB_OUT + NB_X + NB_W1 + NB_W2, 256>>>(out, x, w1, w2);  // 2

  const int smem = 4 * 2 * 128 * 40 * 2;  // 81920 B
  cudaFuncSetAttribute(moe_mma<0>, cudaFuncAttributeMaxDynamicSharedMemorySize, smem);
  cudaFuncSetAttribute(moe_mma<1>, cudaFuncAttributeMaxDynamicSharedMemorySize, smem);
  moe_mma<0><<<dim3(DHID / 128, MAXT), 256, smem>>>(b1, nullptr);       // 3 (ncu slot)
  moe_mma<1><<<dim3(DOUT / 128, MAXT), 256, smem>>>(b2, out);           // 4
}